// round 2
// baseline (speedup 1.0000x reference)
#include <cuda_runtime.h>
#include <mma.h>

using namespace nvcuda;

#define B_   32
#define CIN  96
#define HH   56
#define WW   56
#define HW   3136      // 56*56
#define P0   384
#define P1   72
#define EPS  1e-5f

// Scratch (no cudaMalloc allowed)
__device__ float g_h1[B_ * P0 * HW];   // expand output
__device__ float g_h2[B_ * P0 * HW];   // depthwise output

// ---------------------------------------------------------------------------
// Kernel 1: 1x1 expand (96 -> 384) + BN1 + ReLU6 via wmma tf32.
// Per image GEMM: C[384 x 3136] = We[384 x 96] * X[96 x 3136]
// Block tile M=128 (channels) x N=64 (pixels), full K=96 in smem.
// 8 warps: 4 along M x 2 along N; each warp 32x32 = 2x2 wmma(16x16x8) tiles.
// Dynamic smem: A[128][104] + B[96][72]  (80,896 B)
// grid = (49, 3, 32), block = 256
// ---------------------------------------------------------------------------
#define EA_LD 104   // A leading dim (K padded)
#define EB_LD 72    // B leading dim (N padded)
#define EC_LD 72    // C smem leading dim

__global__ __launch_bounds__(256)
void expand_kernel(const float* __restrict__ x,
                   const float* __restrict__ we,
                   const float* __restrict__ g1, const float* __restrict__ b1,
                   const float* __restrict__ m1, const float* __restrict__ v1)
{
    extern __shared__ float sm[];
    float* As = sm;                    // [128][EA_LD]  (M x K)
    float* Bs = sm + 128 * EA_LD;      // [96][EB_LD]   (K x N)
    float* Cs = sm;                    // reuse: [128][EC_LD]

    const int tid   = threadIdx.x;
    const int wid   = tid >> 5;
    const int nBase = blockIdx.x * 64;
    const int mBase = blockIdx.y * 128;
    const int b     = blockIdx.z;

    const int wm = (wid & 3) * 32;     // warp M offset
    const int wn = (wid >> 2) * 32;    // warp N offset

    // Load A: As[m][k] = tf32(we[(mBase+m)*96 + k]), m in [0,128), k in [0,96)
    for (int t = tid; t < 128 * 96; t += 256) {
        int m = t / 96, k = t - m * 96;
        As[m * EA_LD + k] = wmma::__float_to_tf32(we[(mBase + m) * CIN + k]);
    }
    // Load B: Bs[k][p] = tf32(x[b][k][nBase+p])
    for (int t = tid; t < 96 * 64; t += 256) {
        int k = t >> 6, p = t & 63;
        Bs[k * EB_LD + p] = wmma::__float_to_tf32(x[(b * CIN + k) * HW + nBase + p]);
    }
    __syncthreads();

    wmma::fragment<wmma::accumulator, 16, 16, 8, float> acc[2][2];
    #pragma unroll
    for (int i = 0; i < 2; i++)
        #pragma unroll
        for (int j = 0; j < 2; j++) wmma::fill_fragment(acc[i][j], 0.f);

    #pragma unroll
    for (int k0 = 0; k0 < 96; k0 += 8) {
        wmma::fragment<wmma::matrix_a, 16, 16, 8, wmma::precision::tf32, wmma::row_major> af[2];
        wmma::fragment<wmma::matrix_b, 16, 16, 8, wmma::precision::tf32, wmma::row_major> bf[2];
        #pragma unroll
        for (int i = 0; i < 2; i++)
            wmma::load_matrix_sync(af[i], &As[(wm + i * 16) * EA_LD + k0], EA_LD);
        #pragma unroll
        for (int j = 0; j < 2; j++)
            wmma::load_matrix_sync(bf[j], &Bs[k0 * EB_LD + wn + j * 16], EB_LD);
        #pragma unroll
        for (int i = 0; i < 2; i++)
            #pragma unroll
            for (int j = 0; j < 2; j++)
                wmma::mma_sync(acc[i][j], af[i], bf[j], acc[i][j]);
    }

    __syncthreads();   // done reading As/Bs; reuse as Cs
    #pragma unroll
    for (int i = 0; i < 2; i++)
        #pragma unroll
        for (int j = 0; j < 2; j++)
            wmma::store_matrix_sync(&Cs[(wm + i * 16) * EC_LD + wn + j * 16],
                                    acc[i][j], EC_LD, wmma::mem_row_major);
    __syncthreads();

    // Epilogue: BN + ReLU6, float4 out. 128 rows x 64 cols, 256 threads.
    // Each iteration: 16 rows (16 threads per row, 4 floats each).
    #pragma unroll
    for (int it = 0; it < 8; it++) {
        int row = it * 16 + (tid >> 4);
        int col = (tid & 15) * 4;
        int o = mBase + row;
        float sc = g1[o] * rsqrtf(v1[o] + EPS);
        float sh = b1[o] - m1[o] * sc;
        const float* c = &Cs[row * EC_LD + col];
        float4 v;
        v.x = fminf(fmaxf(c[0] * sc + sh, 0.f), 6.f);
        v.y = fminf(fmaxf(c[1] * sc + sh, 0.f), 6.f);
        v.z = fminf(fmaxf(c[2] * sc + sh, 0.f), 6.f);
        v.w = fminf(fmaxf(c[3] * sc + sh, 0.f), 6.f);
        *(float4*)&g_h1[(b * P0 + o) * HW + nBase + col] = v;
    }
}

// ---------------------------------------------------------------------------
// Kernel 2: 3x3 depthwise + BN2 + ReLU6 (fp32, memory-bound) -> g_h2.
// grid = (7, 384, 32), block = (56, 8)
// ---------------------------------------------------------------------------
__global__ __launch_bounds__(448)
void dw_kernel(const float* __restrict__ dw,
               const float* __restrict__ g2, const float* __restrict__ b2,
               const float* __restrict__ m2, const float* __restrict__ v2)
{
    __shared__ float s[10][58];

    const int tx  = threadIdx.x;
    const int ty  = threadIdx.y;
    const int tid = ty * 56 + tx;
    const int y0  = blockIdx.x * 8;
    const int c   = blockIdx.y;
    const int b   = blockIdx.z;

    const float* src = g_h1 + (b * P0 + c) * HW;

    for (int t = tid; t < 10 * 58; t += 448) {
        int r = t / 58, q = t % 58;
        int y = y0 - 1 + r, xx = q - 1;
        float v = 0.f;
        if (y >= 0 && y < HH && xx >= 0 && xx < WW) v = src[y * WW + xx];
        s[r][q] = v;
    }
    __syncthreads();

    float w[9];
    #pragma unroll
    for (int i = 0; i < 9; i++) w[i] = dw[c * 9 + i];

    float acc = 0.f;
    #pragma unroll
    for (int dy = 0; dy < 3; dy++)
        #pragma unroll
        for (int dx = 0; dx < 3; dx++)
            acc = fmaf(w[dy * 3 + dx], s[ty + dy][tx + dx], acc);

    float sc = g2[c] * rsqrtf(v2[c] + EPS);
    float sh = b2[c] - m2[c] * sc;
    g_h2[(b * P0 + c) * HW + (y0 + ty) * WW + tx] =
        fminf(fmaxf(acc * sc + sh, 0.f), 6.f);
}

// ---------------------------------------------------------------------------
// Kernel 3: 1x1 project (384 -> 72) + BN3 + scatter + residual via wmma tf32.
// Per image GEMM: P[72 x 3136] = Wp[72 x 384] * H2[384 x 3136]
// Block tile M=80 (rows 72..79 zero-padded) x N=64, K chunk 64.
// 10 warps (320 thr): warp w -> m tile (w%5), n pair 2 tiles at (w/5)*32.
// Static smem: Ws[80][72] + Hs[64][72] = 41.5 KB
// grid = (49, 1, 32), block = 320
// ---------------------------------------------------------------------------
#define PW_LD 72
#define PH_LD 72
#define PC_LD 72

__global__ __launch_bounds__(320)
void project_kernel(const float* __restrict__ x,
                    const float* __restrict__ wp,
                    const float* __restrict__ g3, const float* __restrict__ b3,
                    const float* __restrict__ m3, const float* __restrict__ v3,
                    const int* __restrict__ idx,
                    float* __restrict__ out)
{
    __shared__ float Ws[80 * PW_LD];   // M x Kchunk
    __shared__ float Hs[64 * PH_LD];   // Kchunk x N

    const int tid = threadIdx.x;
    const int wid = tid >> 5;
    const int p0  = blockIdx.x * 64;
    const int b   = blockIdx.z;

    const int wm = (wid % 5) * 16;         // warp M offset (0..64)
    const int wn = (wid / 5) * 32;         // warp N offset (0 or 32)

    wmma::fragment<wmma::accumulator, 16, 16, 8, float> acc[2];
    wmma::fill_fragment(acc[0], 0.f);
    wmma::fill_fragment(acc[1], 0.f);

    for (int k0 = 0; k0 < P0; k0 += 64) {
        __syncthreads();
        // Ws[m][k] = tf32(wp[m*384 + k0+k]), rows 72..79 zero
        for (int t = tid; t < 80 * 64; t += 320) {
            int m = t >> 6, k = t & 63;
            float v = (m < P1) ? wp[m * P0 + k0 + k] : 0.f;
            Ws[m * PW_LD + k] = wmma::__float_to_tf32(v);
        }
        // Hs[k][p] = tf32(g_h2[b][k0+k][p0+p])
        for (int t = tid; t < 64 * 64; t += 320) {
            int k = t >> 6, p = t & 63;
            Hs[k * PH_LD + p] = wmma::__float_to_tf32(g_h2[(b * P0 + k0 + k) * HW + p0 + p]);
        }
        __syncthreads();

        #pragma unroll
        for (int kk = 0; kk < 64; kk += 8) {
            wmma::fragment<wmma::matrix_a, 16, 16, 8, wmma::precision::tf32, wmma::row_major> af;
            wmma::fragment<wmma::matrix_b, 16, 16, 8, wmma::precision::tf32, wmma::row_major> bf[2];
            wmma::load_matrix_sync(af, &Ws[wm * PW_LD + kk], PW_LD);
            wmma::load_matrix_sync(bf[0], &Hs[kk * PH_LD + wn], PH_LD);
            wmma::load_matrix_sync(bf[1], &Hs[kk * PH_LD + wn + 16], PH_LD);
            wmma::mma_sync(acc[0], af, bf[0], acc[0]);
            wmma::mma_sync(acc[1], af, bf[1], acc[1]);
        }
    }

    __syncthreads();   // reuse Ws as C tile [80][PC_LD]
    float* Cs = Ws;
    wmma::store_matrix_sync(&Cs[wm * PC_LD + wn],      acc[0], PC_LD, wmma::mem_row_major);
    wmma::store_matrix_sync(&Cs[wm * PC_LD + wn + 16], acc[1], PC_LD, wmma::mem_row_major);
    __syncthreads();

    // Epilogue: BN3 + scatter(idx) + residual. 72 rows x 64 cols (float4).
    for (int t = tid; t < P1 * 16; t += 320) {
        int o   = t >> 4;
        int col = (t & 15) * 4;
        float sc = g3[o] * rsqrtf(v3[o] + EPS);
        float sh = b3[o] - m3[o] * sc;
        int co = idx[o];
        int base = (b * CIN + co) * HW + p0 + col;
        float4 xv = *(const float4*)&x[base];
        const float* c = &Cs[o * PC_LD + col];
        float4 v;
        v.x = xv.x + (c[0] * sc + sh);
        v.y = xv.y + (c[1] * sc + sh);
        v.z = xv.z + (c[2] * sc + sh);
        v.w = xv.w + (c[3] * sc + sh);
        *(float4*)&out[base] = v;
    }
}

// ---------------------------------------------------------------------------
extern "C" void kernel_launch(void* const* d_in, const int* in_sizes, int n_in,
                              void* d_out, int out_size)
{
    const float* x  = (const float*)d_in[0];
    const float* we = (const float*)d_in[1];
    const float* dw = (const float*)d_in[2];
    const float* wp = (const float*)d_in[3];
    const float* g1 = (const float*)d_in[4];
    const float* b1 = (const float*)d_in[5];
    const float* m1 = (const float*)d_in[6];
    const float* v1 = (const float*)d_in[7];
    const float* g2 = (const float*)d_in[8];
    const float* b2 = (const float*)d_in[9];
    const float* m2 = (const float*)d_in[10];
    const float* v2 = (const float*)d_in[11];
    const float* g3 = (const float*)d_in[12];
    const float* b3 = (const float*)d_in[13];
    const float* m3 = (const float*)d_in[14];
    const float* v3 = (const float*)d_in[15];
    const int*   idx = (const int*)d_in[16];
    float* out = (float*)d_out;

    // Residual identity for all channels; preserved ones overwritten by project.
    cudaMemcpyAsync(out, x, (size_t)B_ * CIN * HW * sizeof(float),
                    cudaMemcpyDeviceToDevice, 0);

    {
        const int smem = (128 * EA_LD + 96 * EB_LD) * sizeof(float);  // 80,896 B
        cudaFuncSetAttribute(expand_kernel,
                             cudaFuncAttributeMaxDynamicSharedMemorySize, smem);
        dim3 grid(HW / 64, P0 / 128, B_);   // (49, 3, 32)
        expand_kernel<<<grid, 256, smem>>>(x, we, g1, b1, m1, v1);
    }
    {
        dim3 grid(HH / 8, P0, B_);          // (7, 384, 32)
        dim3 block(WW, 8);
        dw_kernel<<<grid, block>>>(dw, g2, b2, m2, v2);
    }
    {
        dim3 grid(HW / 64, 1, B_);          // (49, 1, 32)
        project_kernel<<<grid, 320>>>(x, wp, g3, b3, m3, v3, idx, out);
    }
}